// round 15
// baseline (speedup 1.0000x reference)
#include <cuda_runtime.h>
#include <math.h>

#define B_ 4
#define S_ 4096
#define D_ 512
#define L_ 8921
#define NCHUNK 32   // l-chunks for column-sum partials

// Scratch (allocation-free rule: __device__ globals)
__device__ float g_weights[B_ * S_ * D_];            // 32 MB: tanh(x@W1^T), [b*s, a]
__device__ float g_colpart[NCHUNK * B_ * S_];        // 2 MB: partial column sums
__device__ float g_colsum[B_ * S_];                  // 64 KB
__device__ float g_partial[16 * B_ * D_];            // out partials

// ---------------- packed f32x2 helpers (Blackwell FFMA2 path) ----------------
__device__ __forceinline__ unsigned long long pack2(float lo, float hi) {
    unsigned long long r;
    asm("mov.b64 %0, {%1,%2};" : "=l"(r) : "f"(lo), "f"(hi));
    return r;
}
__device__ __forceinline__ void fma2(unsigned long long& d, unsigned long long a,
                                     unsigned long long b) {
    asm("fma.rn.f32x2 %0, %1, %2, %0;" : "+l"(d) : "l"(a), "l"(b));
}
__device__ __forceinline__ float2 unpack2(unsigned long long v) {
    float2 f;
    asm("mov.b64 {%0,%1}, %2;" : "=f"(f.x), "=f"(f.y) : "l"(v));
    return f;
}

// ---------------------------------------------------------------------------
// C[M,N] = op( A[M,K] @ B[N,K]^T ), both A and B row-major K-contiguous (TN).
// 128x128x16 tiles, 256 threads, 8x8 per-thread microtile via fma.rn.f32x2.
// blockIdx.z batches the B and C operands (A shared across batch).
// ---------------------------------------------------------------------------
template <bool TANH, bool GUARD_M>
__global__ void __launch_bounds__(256, 2)
sgemm_tn(const float* __restrict__ Ag, const float* __restrict__ Bg,
         float* __restrict__ Cg, int M, int N, int K,
         long long bStrideB, long long bStrideC) {
    const float* A = Ag;
    const float* Bm = Bg + (long long)blockIdx.z * bStrideB;
    float* C = Cg + (long long)blockIdx.z * bStrideC;

    __shared__ float As[16][132];   // transposed A tile, padded
    __shared__ float Bs[16][128];   // transposed B tile

    const int tid = threadIdx.x;
    const int tx = tid & 15;   // n direction (8 cols each)
    const int ty = tid >> 4;   // m direction (8 rows each)
    const int m0 = blockIdx.y * 128;
    const int n0 = blockIdx.x * 128;

    const int lrow = tid >> 2;         // 0..63
    const int lcol = (tid & 3) * 4;    // 0,4,8,12

    unsigned long long acc[8][4];
#pragma unroll
    for (int i = 0; i < 8; i++)
#pragma unroll
        for (int j = 0; j < 4; j++) acc[i][j] = 0ULL;

    for (int kt = 0; kt < K; kt += 16) {
        // ---- A tile: rows m0+lrow(+64), cols kt+lcol..+3, store transposed
#pragma unroll
        for (int h = 0; h < 2; h++) {
            const int r = lrow + h * 64;
            const int gm = m0 + r;
            float4 v = make_float4(0.f, 0.f, 0.f, 0.f);
            if (!GUARD_M || gm < M)
                v = *(const float4*)&A[(long long)gm * K + kt + lcol];
            As[lcol + 0][r] = v.x;
            As[lcol + 1][r] = v.y;
            As[lcol + 2][r] = v.z;
            As[lcol + 3][r] = v.w;
        }
        // ---- B tile (N is always a multiple of 128 here)
#pragma unroll
        for (int h = 0; h < 2; h++) {
            const int r = lrow + h * 64;
            float4 v = *(const float4*)&Bm[(long long)(n0 + r) * K + kt + lcol];
            Bs[lcol + 0][r] = v.x;
            Bs[lcol + 1][r] = v.y;
            Bs[lcol + 2][r] = v.z;
            Bs[lcol + 3][r] = v.w;
        }
        __syncthreads();

#pragma unroll
        for (int k = 0; k < 16; k++) {
            const float4 a0 = *(const float4*)&As[k][ty * 8];
            const float4 a1 = *(const float4*)&As[k][ty * 8 + 4];
            const ulonglong2 bq0 = *(const ulonglong2*)&Bs[k][tx * 8];
            const ulonglong2 bq1 = *(const ulonglong2*)&Bs[k][tx * 8 + 4];
            unsigned long long ad[8];
            ad[0] = pack2(a0.x, a0.x);
            ad[1] = pack2(a0.y, a0.y);
            ad[2] = pack2(a0.z, a0.z);
            ad[3] = pack2(a0.w, a0.w);
            ad[4] = pack2(a1.x, a1.x);
            ad[5] = pack2(a1.y, a1.y);
            ad[6] = pack2(a1.z, a1.z);
            ad[7] = pack2(a1.w, a1.w);
            unsigned long long bp[4] = {bq0.x, bq0.y, bq1.x, bq1.y};
#pragma unroll
            for (int i = 0; i < 8; i++)
#pragma unroll
                for (int j = 0; j < 4; j++) fma2(acc[i][j], ad[i], bp[j]);
        }
        __syncthreads();
    }

    // ---- epilogue
#pragma unroll
    for (int i = 0; i < 8; i++) {
        const int gm = m0 + ty * 8 + i;
        if (GUARD_M && gm >= M) continue;
        float2 p0 = unpack2(acc[i][0]);
        float2 p1 = unpack2(acc[i][1]);
        float2 p2 = unpack2(acc[i][2]);
        float2 p3 = unpack2(acc[i][3]);
        float4 o0 = make_float4(p0.x, p0.y, p1.x, p1.y);
        float4 o1 = make_float4(p2.x, p2.y, p3.x, p3.y);
        if (TANH) {
            o0.x = tanhf(o0.x); o0.y = tanhf(o0.y);
            o0.z = tanhf(o0.z); o0.w = tanhf(o0.w);
            o1.x = tanhf(o1.x); o1.y = tanhf(o1.y);
            o1.z = tanhf(o1.z); o1.w = tanhf(o1.w);
        }
        *(float4*)&C[(long long)gm * N + n0 + tx * 8] = o0;
        *(float4*)&C[(long long)gm * N + n0 + tx * 8 + 4] = o1;
    }
}

// ---------------------------------------------------------------------------
// In-place softmax over the contiguous S dim. One block per (b,l) row.
// ---------------------------------------------------------------------------
__global__ void __launch_bounds__(512) softmax_rows(float* __restrict__ att) {
    __shared__ float red[16];
    const long long row = blockIdx.x;
    float* p = att + row * (long long)S_;
    const int tid = threadIdx.x;

    float4 v0 = ((const float4*)p)[tid];
    float4 v1 = ((const float4*)p)[tid + 512];

    float mx = fmaxf(fmaxf(fmaxf(v0.x, v0.y), fmaxf(v0.z, v0.w)),
                     fmaxf(fmaxf(v1.x, v1.y), fmaxf(v1.z, v1.w)));
#pragma unroll
    for (int o = 16; o > 0; o >>= 1) mx = fmaxf(mx, __shfl_xor_sync(0xffffffffu, mx, o));
    if ((tid & 31) == 0) red[tid >> 5] = mx;
    __syncthreads();
    if (tid < 32) {
        float m2 = (tid < 16) ? red[tid] : -3.402823466e38f;
#pragma unroll
        for (int o = 8; o > 0; o >>= 1) m2 = fmaxf(m2, __shfl_xor_sync(0xffffffffu, m2, o));
        if (tid == 0) red[0] = m2;
    }
    __syncthreads();
    mx = red[0];
    __syncthreads();  // everyone has read red[0] before it is reused

    v0.x = __expf(v0.x - mx); v0.y = __expf(v0.y - mx);
    v0.z = __expf(v0.z - mx); v0.w = __expf(v0.w - mx);
    v1.x = __expf(v1.x - mx); v1.y = __expf(v1.y - mx);
    v1.z = __expf(v1.z - mx); v1.w = __expf(v1.w - mx);

    float sm = (v0.x + v0.y + v0.z + v0.w) + (v1.x + v1.y + v1.z + v1.w);
#pragma unroll
    for (int o = 16; o > 0; o >>= 1) sm += __shfl_xor_sync(0xffffffffu, sm, o);
    if ((tid & 31) == 0) red[tid >> 5] = sm;
    __syncthreads();
    if (tid < 32) {
        float s2 = (tid < 16) ? red[tid] : 0.f;
#pragma unroll
        for (int o = 8; o > 0; o >>= 1) s2 += __shfl_xor_sync(0xffffffffu, s2, o);
        if (tid == 0) red[0] = s2;
    }
    __syncthreads();
    const float inv = 1.0f / red[0];

    v0.x *= inv; v0.y *= inv; v0.z *= inv; v0.w *= inv;
    v1.x *= inv; v1.y *= inv; v1.z *= inv; v1.w *= inv;
    ((float4*)p)[tid] = v0;
    ((float4*)p)[tid + 512] = v1;
}

// ---------------------------------------------------------------------------
// colsum[b,s] = sum_l att[b,l,s]  — two-stage, deterministic (no atomics)
// ---------------------------------------------------------------------------
__global__ void __launch_bounds__(256) colsum_partial(const float* __restrict__ att) {
    const int s = blockIdx.x * 256 + threadIdx.x;
    const int ch = blockIdx.y;
    const int b = blockIdx.z;
    const int LCH = (L_ + NCHUNK - 1) / NCHUNK;  // 279
    const int l0 = ch * LCH;
    const int l1 = min(l0 + LCH, L_);
    const float* p = att + (long long)b * L_ * S_ + s;
    float a0 = 0.f, a1 = 0.f, a2 = 0.f, a3 = 0.f;
    int l = l0;
    for (; l + 4 <= l1; l += 4) {
        a0 += p[(long long)(l + 0) * S_];
        a1 += p[(long long)(l + 1) * S_];
        a2 += p[(long long)(l + 2) * S_];
        a3 += p[(long long)(l + 3) * S_];
    }
    for (; l < l1; l++) a0 += p[(long long)l * S_];
    g_colpart[((long long)ch * B_ + b) * S_ + s] = (a0 + a1) + (a2 + a3);
}

__global__ void __launch_bounds__(256) colsum_reduce() {
    const int s = blockIdx.x * 256 + threadIdx.x;
    const int b = blockIdx.y;
    float acc = 0.f;
#pragma unroll
    for (int ch = 0; ch < NCHUNK; ch++) acc += g_colpart[((long long)ch * B_ + b) * S_ + s];
    g_colsum[b * S_ + s] = acc;
}

// ---------------------------------------------------------------------------
// out[b,d] = (sum_s colsum[b,s] * x[b,s,d]) / R — two-stage, deterministic
// ---------------------------------------------------------------------------
__global__ void __launch_bounds__(512) out_partial_kernel(const float* __restrict__ x) {
    const int b = blockIdx.y;
    const int ch = blockIdx.x;  // 16 chunks of 256 s each
    const int d = threadIdx.x;
    const int sbase = ch * 256;
    float acc = 0.f;
    for (int i = 0; i < 256; i++) {
        const int s = sbase + i;
        acc += g_colsum[b * S_ + s] * x[((long long)(b * S_ + s)) * D_ + d];
    }
    g_partial[(ch * B_ + b) * D_ + d] = acc;
}

__global__ void __launch_bounds__(512) out_final_kernel(float* __restrict__ out) {
    const int b = blockIdx.x;
    const int d = threadIdx.x;
    float acc = 0.f;
#pragma unroll
    for (int ch = 0; ch < 16; ch++) acc += g_partial[(ch * B_ + b) * D_ + d];
    out[b * D_ + d] = acc * (1.0f / 8921.0f);
}

// ---------------------------------------------------------------------------
extern "C" void kernel_launch(void* const* d_in, const int* in_sizes, int n_in,
                              void* d_out, int out_size) {
    const float* x = (const float*)d_in[0];    // [B,S,D]
    const float* W1 = (const float*)d_in[1];   // [D,D]
    const float* W2 = (const float*)d_in[2];   // [L,D]
    float* out = (float*)d_out;

    const long long attElems = (long long)B_ * L_ * S_;
    // Tuple output (out, att_weights) flattened in order: out first, att last.
    float* att = out + ((long long)out_size - attElems);

    float* wbuf = nullptr;
    cudaGetSymbolAddress((void**)&wbuf, g_weights);

    // 1) weights = tanh(x @ W1^T)   [16384, 512]
    {
        dim3 grid(D_ / 128, (B_ * S_) / 128, 1);
        sgemm_tn<true, false><<<grid, 256>>>(x, W1, wbuf, B_ * S_, D_, D_, 0LL, 0LL);
    }
    // 2) logits[b,l,s] = W2 @ weights_b^T  -> written directly into att region
    {
        dim3 grid(S_ / 128, (L_ + 127) / 128, B_);
        sgemm_tn<false, true><<<grid, 256>>>(W2, wbuf, att, L_, S_, D_,
                                             (long long)S_ * D_, (long long)L_ * S_);
    }
    // 3) in-place softmax over S per (b,l) row
    softmax_rows<<<B_ * L_, 512>>>(att);

    // 4) colsum[b,s] = sum_l att[b,l,s]
    {
        dim3 grid(S_ / 256, NCHUNK, B_);
        colsum_partial<<<grid, 256>>>(att);
        dim3 grid2(S_ / 256, B_);
        colsum_reduce<<<grid2, 256>>>();
    }
    // 5) out[b,d] = sum_s colsum[b,s] * x[b,s,d] / R
    {
        dim3 grid(16, B_);
        out_partial_kernel<<<grid, 512>>>(x);
        out_final_kernel<<<B_, 512>>>(out);
    }
}

// round 17
// speedup vs baseline: 3.1320x; 3.1320x over previous
#include <cuda_runtime.h>
#include <math.h>
#include <stdint.h>

#define B_ 4
#define S_ 4096
#define D_ 512
#define L_ 8921
#define NCHUNK 32

// Scratch (allocation-free rule: __device__ globals)
__device__ float g_weights[B_ * S_ * D_];     // 32 MB: tf32(tanh(x@W1^T))
__device__ float g_w2t[L_ * D_];              // 18 MB: tf32-rounded W2
__device__ float g_colpart[NCHUNK * B_ * S_];
__device__ float g_colsum[B_ * S_];
__device__ float g_partial[16 * B_ * D_];

// ---------------- helpers ----------------
__device__ __forceinline__ float tf32r(float x) {
    uint32_t u;
    asm("cvt.rna.tf32.f32 %0, %1;" : "=r"(u) : "f"(x));
    return __uint_as_float(u);
}
__device__ __forceinline__ unsigned long long pack2(float lo, float hi) {
    unsigned long long r;
    asm("mov.b64 %0, {%1,%2};" : "=l"(r) : "f"(lo), "f"(hi));
    return r;
}
__device__ __forceinline__ void fma2(unsigned long long& d, unsigned long long a,
                                     unsigned long long b) {
    asm("fma.rn.f32x2 %0, %1, %2, %0;" : "+l"(d) : "l"(a), "l"(b));
}
__device__ __forceinline__ float2 unpack2(unsigned long long v) {
    float2 f;
    asm("mov.b64 {%0,%1}, %2;" : "=f"(f.x), "=f"(f.y) : "l"(v));
    return f;
}
__device__ __forceinline__ uint32_t smem_u32(const void* p) {
    uint32_t a;
    asm("{ .reg .u64 t; cvta.to.shared.u64 t, %1; cvt.u32.u64 %0, t; }" : "=r"(a) : "l"(p));
    return a;
}
__device__ __forceinline__ void cp16(uint32_t dst, const void* src, int sz) {
    asm volatile("cp.async.cg.shared.global [%0], [%1], 16, %2;"
                 :: "r"(dst), "l"(src), "r"(sz) : "memory");
}
#define CP_COMMIT() asm volatile("cp.async.commit_group;" ::: "memory")
#define CP_WAIT1() asm volatile("cp.async.wait_group 1;" ::: "memory")

__device__ __forceinline__ void ldsm4(uint32_t* r, uint32_t addr) {
    asm volatile("ldmatrix.sync.aligned.m8n8.x4.shared.b16 {%0,%1,%2,%3}, [%4];"
                 : "=r"(r[0]), "=r"(r[1]), "=r"(r[2]), "=r"(r[3]) : "r"(addr));
}
__device__ __forceinline__ void mma_tf32(float* c, const uint32_t* a, uint32_t b0,
                                         uint32_t b1) {
    asm volatile(
        "mma.sync.aligned.m16n8k8.row.col.f32.tf32.tf32.f32 "
        "{%0,%1,%2,%3}, {%4,%5,%6,%7}, {%8,%9}, {%0,%1,%2,%3};"
        : "+f"(c[0]), "+f"(c[1]), "+f"(c[2]), "+f"(c[3])
        : "r"(a[0]), "r"(a[1]), "r"(a[2]), "r"(a[3]), "r"(b0), "r"(b1));
}

// ---------------------------------------------------------------------------
// W2 -> tf32-rounded copy
// ---------------------------------------------------------------------------
__global__ void __launch_bounds__(256) cvt_w2_kernel(const float* __restrict__ w2) {
    const int i = blockIdx.x * 256 + threadIdx.x;
    const int n4 = (L_ * D_) / 4;
    if (i < n4) {
        float4 v = ((const float4*)w2)[i];
        v.x = tf32r(v.x); v.y = tf32r(v.y); v.z = tf32r(v.z); v.w = tf32r(v.w);
        ((float4*)g_w2t)[i] = v;
    }
}

// ---------------------------------------------------------------------------
// GEMM1: C = tf32(tanh(A @ B^T)), FFMA2 SGEMM (8.6 GFLOP, exact fp32 math)
// ---------------------------------------------------------------------------
__global__ void __launch_bounds__(256, 2)
sgemm1(const float* __restrict__ A, const float* __restrict__ Bm,
       float* __restrict__ C, int M, int N, int K) {
    __shared__ float As[16][132];
    __shared__ float Bs[16][128];

    const int tid = threadIdx.x;
    const int tx = tid & 15;
    const int ty = tid >> 4;
    const int m0 = blockIdx.y * 128;
    const int n0 = blockIdx.x * 128;
    const int lrow = tid >> 2;
    const int lcol = (tid & 3) * 4;

    unsigned long long acc[8][4];
#pragma unroll
    for (int i = 0; i < 8; i++)
#pragma unroll
        for (int j = 0; j < 4; j++) acc[i][j] = 0ULL;

    for (int kt = 0; kt < K; kt += 16) {
#pragma unroll
        for (int h = 0; h < 2; h++) {
            const int r = lrow + h * 64;
            float4 v = *(const float4*)&A[(long long)(m0 + r) * K + kt + lcol];
            As[lcol + 0][r] = v.x; As[lcol + 1][r] = v.y;
            As[lcol + 2][r] = v.z; As[lcol + 3][r] = v.w;
        }
#pragma unroll
        for (int h = 0; h < 2; h++) {
            const int r = lrow + h * 64;
            float4 v = *(const float4*)&Bm[(long long)(n0 + r) * K + kt + lcol];
            Bs[lcol + 0][r] = v.x; Bs[lcol + 1][r] = v.y;
            Bs[lcol + 2][r] = v.z; Bs[lcol + 3][r] = v.w;
        }
        __syncthreads();
#pragma unroll
        for (int k = 0; k < 16; k++) {
            const float4 a0 = *(const float4*)&As[k][ty * 8];
            const float4 a1 = *(const float4*)&As[k][ty * 8 + 4];
            const ulonglong2 bq0 = *(const ulonglong2*)&Bs[k][tx * 8];
            const ulonglong2 bq1 = *(const ulonglong2*)&Bs[k][tx * 8 + 4];
            unsigned long long ad[8];
            ad[0] = pack2(a0.x, a0.x); ad[1] = pack2(a0.y, a0.y);
            ad[2] = pack2(a0.z, a0.z); ad[3] = pack2(a0.w, a0.w);
            ad[4] = pack2(a1.x, a1.x); ad[5] = pack2(a1.y, a1.y);
            ad[6] = pack2(a1.z, a1.z); ad[7] = pack2(a1.w, a1.w);
            unsigned long long bp[4] = {bq0.x, bq0.y, bq1.x, bq1.y};
#pragma unroll
            for (int i = 0; i < 8; i++)
#pragma unroll
                for (int j = 0; j < 4; j++) fma2(acc[i][j], ad[i], bp[j]);
        }
        __syncthreads();
    }

#pragma unroll
    for (int i = 0; i < 8; i++) {
        const int gm = m0 + ty * 8 + i;
        float2 p0 = unpack2(acc[i][0]);
        float2 p1 = unpack2(acc[i][1]);
        float2 p2 = unpack2(acc[i][2]);
        float2 p3 = unpack2(acc[i][3]);
        float4 o0 = make_float4(tf32r(tanhf(p0.x)), tf32r(tanhf(p0.y)),
                                tf32r(tanhf(p1.x)), tf32r(tanhf(p1.y)));
        float4 o1 = make_float4(tf32r(tanhf(p2.x)), tf32r(tanhf(p2.y)),
                                tf32r(tanhf(p3.x)), tf32r(tanhf(p3.y)));
        *(float4*)&C[(long long)gm * N + n0 + tx * 8] = o0;
        *(float4*)&C[(long long)gm * N + n0 + tx * 8 + 4] = o1;
    }
}

// ---------------------------------------------------------------------------
// GEMM2: logits[b,l,s] = W2t[l,:] . weights[b,s,:]   (tf32 mma.sync path)
// 128x128x32 CTA tile, 256 thr (2x4 warps, 64x32 warp tile), cp.async x2 stage.
// ---------------------------------------------------------------------------
#define G2_SMEM (2 * (16384 + 16384))

__global__ void __launch_bounds__(256, 2)
gemm2_mma(const float* __restrict__ Wt, const float* __restrict__ Wg,
          float* __restrict__ att) {
    extern __shared__ char smem_raw[];
    const uint32_t base = smem_u32(smem_raw);
    // stage s: A at base + s*32768, B at base + s*32768 + 16384
    const int tid = threadIdx.x;
    const int wid = tid >> 5;
    const int lane = tid & 31;
    const int wm = wid >> 2;  // 0..1, 64 rows each
    const int wn = wid & 3;   // 0..3, 32 cols each
    const int m0 = blockIdx.y * 128;
    const int n0 = blockIdx.x * 128;
    const int b = blockIdx.z;
    const float* Bb = Wg + (long long)b * S_ * D_;
    float* Cb = att + (long long)b * L_ * S_;

    float acc[4][4][4];
#pragma unroll
    for (int i = 0; i < 4; i++)
#pragma unroll
        for (int j = 0; j < 4; j++)
#pragma unroll
            for (int k = 0; k < 4; k++) acc[i][j][k] = 0.f;

    // per-thread load coords (4 chunks of 16B for A, 4 for B per stage)
    const int c_row = tid >> 3;       // base row advances by 32 per p
    const int c_col = tid & 7;        // 16B chunk within row

    auto load_stage = [&](int kt, uint32_t st) {
        const uint32_t As = base + st * 32768u;
        const uint32_t Bs = As + 16384u;
#pragma unroll
        for (int p = 0; p < 4; p++) {
            const int row = c_row + p * 32;
            const int gm = m0 + row;
            const float* src =
                &Wt[(long long)(gm < L_ ? gm : 0) * D_ + kt + c_col * 4];
            const uint32_t dst = As + (uint32_t)(row * 8 + (c_col ^ (row & 7))) * 16u;
            cp16(dst, src, gm < L_ ? 16 : 0);
        }
#pragma unroll
        for (int p = 0; p < 4; p++) {
            const int row = c_row + p * 32;
            const float* src = &Bb[(long long)(n0 + row) * D_ + kt + c_col * 4];
            const uint32_t dst = Bs + (uint32_t)(row * 8 + (c_col ^ (row & 7))) * 16u;
            cp16(dst, src, 16);
        }
        CP_COMMIT();
    };

    // precomputed fragment addressing
    const int a_rb = wm * 64 + (lane & 15);       // row base (mt adds *16)
    const int a_hi = lane >> 4;                   // chunk +0/+1
    const int a_sx = a_rb & 7;
    const int b_rb = wn * 32 + ((lane >> 4) << 3) + (lane & 7);  // +16 per ntp
    const int b_hi = (lane >> 3) & 1;
    const int b_sx = lane & 7;

    auto compute = [&](uint32_t st) {
        const uint32_t As = base + st * 32768u;
        const uint32_t Bs = As + 16384u;
#pragma unroll
        for (int ks = 0; ks < 4; ks++) {
            uint32_t a[4][4], bfr[2][4];
#pragma unroll
            for (int mt = 0; mt < 4; mt++) {
                const int mrow = a_rb + mt * 16;
                const uint32_t ad =
                    As + (uint32_t)mrow * 128u +
                    (uint32_t)((ks * 2 + a_hi) ^ a_sx) * 16u;
                ldsm4(a[mt], ad);
            }
#pragma unroll
            for (int ntp = 0; ntp < 2; ntp++) {
                const int nrow = b_rb + ntp * 16;
                const uint32_t bd =
                    Bs + (uint32_t)nrow * 128u +
                    (uint32_t)((ks * 2 + b_hi) ^ b_sx) * 16u;
                ldsm4(bfr[ntp], bd);
            }
#pragma unroll
            for (int mt = 0; mt < 4; mt++)
#pragma unroll
                for (int nt = 0; nt < 4; nt++)
                    mma_tf32(acc[mt][nt], a[mt], bfr[nt >> 1][(nt & 1) * 2],
                             bfr[nt >> 1][(nt & 1) * 2 + 1]);
        }
    };

    load_stage(0, 0);
    load_stage(32, 1);

#pragma unroll 1
    for (int it = 0; it < 16; it++) {
        CP_WAIT1();
        __syncthreads();
        compute(it & 1);
        __syncthreads();
        if (it + 2 < 16) load_stage((it + 2) * 32, it & 1);
    }

    // epilogue
    const int g = lane >> 2, t = lane & 3;
#pragma unroll
    for (int mt = 0; mt < 4; mt++) {
        const int gm0 = m0 + wm * 64 + mt * 16 + g;
#pragma unroll
        for (int nt = 0; nt < 4; nt++) {
            const long long col = n0 + wn * 32 + nt * 8 + 2 * t;
            if (gm0 < L_)
                *(float2*)&Cb[(long long)gm0 * S_ + col] =
                    make_float2(acc[mt][nt][0], acc[mt][nt][1]);
            if (gm0 + 8 < L_)
                *(float2*)&Cb[(long long)(gm0 + 8) * S_ + col] =
                    make_float2(acc[mt][nt][2], acc[mt][nt][3]);
        }
    }
}

// ---------------------------------------------------------------------------
// In-place softmax over contiguous S per (b,l) row.
// ---------------------------------------------------------------------------
__global__ void __launch_bounds__(512) softmax_rows(float* __restrict__ att) {
    __shared__ float red[16];
    const long long row = blockIdx.x;
    float* p = att + row * (long long)S_;
    const int tid = threadIdx.x;

    float4 v0 = ((const float4*)p)[tid];
    float4 v1 = ((const float4*)p)[tid + 512];

    float mx = fmaxf(fmaxf(fmaxf(v0.x, v0.y), fmaxf(v0.z, v0.w)),
                     fmaxf(fmaxf(v1.x, v1.y), fmaxf(v1.z, v1.w)));
#pragma unroll
    for (int o = 16; o > 0; o >>= 1) mx = fmaxf(mx, __shfl_xor_sync(0xffffffffu, mx, o));
    if ((tid & 31) == 0) red[tid >> 5] = mx;
    __syncthreads();
    if (tid < 32) {
        float m2 = (tid < 16) ? red[tid] : -3.402823466e38f;
#pragma unroll
        for (int o = 8; o > 0; o >>= 1) m2 = fmaxf(m2, __shfl_xor_sync(0xffffffffu, m2, o));
        if (tid == 0) red[0] = m2;
    }
    __syncthreads();
    mx = red[0];
    __syncthreads();

    v0.x = __expf(v0.x - mx); v0.y = __expf(v0.y - mx);
    v0.z = __expf(v0.z - mx); v0.w = __expf(v0.w - mx);
    v1.x = __expf(v1.x - mx); v1.y = __expf(v1.y - mx);
    v1.z = __expf(v1.z - mx); v1.w = __expf(v1.w - mx);

    float sm = (v0.x + v0.y + v0.z + v0.w) + (v1.x + v1.y + v1.z + v1.w);
#pragma unroll
    for (int o = 16; o > 0; o >>= 1) sm += __shfl_xor_sync(0xffffffffu, sm, o);
    if ((tid & 31) == 0) red[tid >> 5] = sm;
    __syncthreads();
    if (tid < 32) {
        float s2 = (tid < 16) ? red[tid] : 0.f;
#pragma unroll
        for (int o = 8; o > 0; o >>= 1) s2 += __shfl_xor_sync(0xffffffffu, s2, o);
        if (tid == 0) red[0] = s2;
    }
    __syncthreads();
    const float inv = 1.0f / red[0];

    v0.x *= inv; v0.y *= inv; v0.z *= inv; v0.w *= inv;
    v1.x *= inv; v1.y *= inv; v1.z *= inv; v1.w *= inv;
    ((float4*)p)[tid] = v0;
    ((float4*)p)[tid + 512] = v1;
}

// ---------------------------------------------------------------------------
// colsum + output reduction (deterministic, no atomics)
// ---------------------------------------------------------------------------
__global__ void __launch_bounds__(256) colsum_partial(const float* __restrict__ att) {
    const int s = blockIdx.x * 256 + threadIdx.x;
    const int ch = blockIdx.y;
    const int b = blockIdx.z;
    const int LCH = (L_ + NCHUNK - 1) / NCHUNK;
    const int l0 = ch * LCH;
    const int l1 = min(l0 + LCH, L_);
    const float* p = att + (long long)b * L_ * S_ + s;
    float a0 = 0.f, a1 = 0.f, a2 = 0.f, a3 = 0.f;
    int l = l0;
    for (; l + 4 <= l1; l += 4) {
        a0 += p[(long long)(l + 0) * S_];
        a1 += p[(long long)(l + 1) * S_];
        a2 += p[(long long)(l + 2) * S_];
        a3 += p[(long long)(l + 3) * S_];
    }
    for (; l < l1; l++) a0 += p[(long long)l * S_];
    g_colpart[((long long)ch * B_ + b) * S_ + s] = (a0 + a1) + (a2 + a3);
}

__global__ void __launch_bounds__(256) colsum_reduce() {
    const int s = blockIdx.x * 256 + threadIdx.x;
    const int b = blockIdx.y;
    float acc = 0.f;
#pragma unroll
    for (int ch = 0; ch < NCHUNK; ch++)
        acc += g_colpart[((long long)ch * B_ + b) * S_ + s];
    g_colsum[b * S_ + s] = acc;
}

__global__ void __launch_bounds__(512) out_partial_kernel(const float* __restrict__ x) {
    const int b = blockIdx.y;
    const int ch = blockIdx.x;
    const int d = threadIdx.x;
    const int sbase = ch * 256;
    float acc = 0.f;
    for (int i = 0; i < 256; i++) {
        const int s = sbase + i;
        acc += g_colsum[b * S_ + s] * x[((long long)(b * S_ + s)) * D_ + d];
    }
    g_partial[(ch * B_ + b) * D_ + d] = acc;
}

__global__ void __launch_bounds__(512) out_final_kernel(float* __restrict__ out) {
    const int b = blockIdx.x;
    const int d = threadIdx.x;
    float acc = 0.f;
#pragma unroll
    for (int ch = 0; ch < 16; ch++) acc += g_partial[(ch * B_ + b) * D_ + d];
    out[b * D_ + d] = acc * (1.0f / 8921.0f);
}

// ---------------------------------------------------------------------------
extern "C" void kernel_launch(void* const* d_in, const int* in_sizes, int n_in,
                              void* d_out, int out_size) {
    const float* x = (const float*)d_in[0];   // [B,S,D]
    const float* W1 = (const float*)d_in[1];  // [D,D]
    const float* W2 = (const float*)d_in[2];  // [L,D]
    float* out = (float*)d_out;

    const long long attElems = (long long)B_ * L_ * S_;
    float* att = out + ((long long)out_size - attElems);

    float* wbuf = nullptr;
    cudaGetSymbolAddress((void**)&wbuf, g_weights);
    float* w2t = nullptr;
    cudaGetSymbolAddress((void**)&w2t, g_w2t);

    // 0) tf32-round W2 once
    {
        const int n4 = (L_ * D_) / 4;
        cvt_w2_kernel<<<(n4 + 255) / 256, 256>>>(W2);
    }
    // 1) weights = tf32(tanh(x @ W1^T))
    {
        dim3 grid(D_ / 128, (B_ * S_) / 128, 1);
        sgemm1<<<grid, 256>>>(x, W1, wbuf, B_ * S_, D_, D_);
    }
    // 2) logits via tf32 mma.sync -> att region
    {
        cudaFuncSetAttribute(gemm2_mma, cudaFuncAttributeMaxDynamicSharedMemorySize,
                             G2_SMEM);
        dim3 grid(S_ / 128, (L_ + 127) / 128, B_);
        gemm2_mma<<<grid, 256, G2_SMEM>>>(w2t, wbuf, att);
    }
    // 3) softmax over S
    softmax_rows<<<B_ * L_, 512>>>(att);
    // 4) colsum
    {
        dim3 grid(S_ / 256, NCHUNK, B_);
        colsum_partial<<<grid, 256>>>(att);
        dim3 grid2(S_ / 256, B_);
        colsum_reduce<<<grid2, 256>>>();
    }
    // 5) out
    {
        dim3 grid(16, B_);
        out_partial_kernel<<<grid, 512>>>(x);
        out_final_kernel<<<B_, 512>>>(out);
    }
}